// round 7
// baseline (speedup 1.0000x reference)
#include <cuda_runtime.h>
#include <cstdint>

#define NQ 14
#define NL 6
#define DIM 16384
#define NG (NL * NQ)                  // 84 rotation gates
#define NTHREADS 1024
#define APT (DIM / NTHREADS)          // 16 amps per thread
#define NWARPS (NTHREADS / 32)        // 32
#define NGROUPS (NL * 3)              // (5,5,4) per layer

typedef unsigned long long u64;

#define PK2(r, a, b)   asm("mov.b64 %0, {%1,%2};" : "=l"(r) : "f"(a), "f"(b))
#define UPK2(a, b, r)  asm("mov.b64 {%0,%1}, %2;" : "=f"(a), "=f"(b) : "l"(r))
#define FMA2(d, a, b, c) asm("fma.rn.f32x2 %0, %1, %2, %3;" : "=l"(d) : "l"(a), "l"(b), "l"(c))
#define MUL2(d, a, b)    asm("mul.rn.f32x2 %0, %1, %2;" : "=l"(d) : "l"(a), "l"(b))

struct Group {
    unsigned short loc2glob[32];  // local coset index -> XOR offset
    unsigned short row[5];        // parity rows (true-qubit bit)
    unsigned char  npos[10];      // non-pivot bit positions
    unsigned char  gbase;         // first gate index
};
struct Tab2 {
    Group grp[NGROUPS];
    unsigned short mrow0, mrow1;
};

// SU(2) form: Rot = [[a, -conj(b)], [b, conj(a)]]; store only a=u00, b=u10.
__device__ float2 g_ab[NG][2];

__global__ void prep_gates_kernel(const float* __restrict__ w) {
    int g = blockIdx.x * blockDim.x + threadIdx.x;
    if (g >= NG) return;
    float phi = w[g*3+0], theta = w[g*3+1], omega = w[g*3+2];
    float st, ct;
    sincosf(theta * 0.5f, &st, &ct);
    float ssp, csp, ssm, csm;
    sincosf(0.5f * (phi + omega), &ssp, &csp);
    sincosf(0.5f * (phi - omega), &ssm, &csm);
    g_ab[g][0] = make_float2( csp * ct, -ssp * ct);   // a = u00
    g_ab[g][1] = make_float2( csm * st, -ssm * st);   // b = u10
}

// Packed butterfly: A=(ax,Ay), B=(Bx,by) already sw-folded.
// n0 = A p - conj(B) q ; n1 = B p + conj(A) q   (p = true-0 slot, q = true-1)
#define BUTTERFLY2(px, py, qx, qy, nx0, ny0, nx1, ny1)                       \
    do {                                                                     \
        MUL2(nx0, snby, qy); FMA2(nx0, snBx, qx, nx0);                       \
        FMA2(nx0, snAy, py, nx0); FMA2(nx0, sax, px, nx0);                   \
        MUL2(ny0, sby, qx); FMA2(ny0, snBx, qy, ny0);                        \
        FMA2(ny0, sAy, px, ny0); FMA2(ny0, sax, py, ny0);                    \
        MUL2(nx1, sAy, qy); FMA2(nx1, sax, qx, nx1);                         \
        FMA2(nx1, snby, py, nx1); FMA2(nx1, sBx, px, nx1);                   \
        MUL2(ny1, snAy, qx); FMA2(ny1, sax, qy, ny1);                        \
        FMA2(ny1, sby, px, ny1); FMA2(ny1, sBx, py, ny1);                    \
    } while (0)

template<int KG>
__device__ __forceinline__ void do_group(float* __restrict__ sx,
                                         float* __restrict__ sy,
                                         const Group& grp, int tid) {
    // KG==5: coset (32 amps) spans a thread pair (tid^1); 16 amps/thread,
    //        local bit4 = tid&1, gate 4 via shfl_xor. KG==4: 1 coset/thread.
    unsigned c, tb4;
    if (KG == 5) { c = (unsigned)tid >> 1; tb4 = ((unsigned)tid & 1u) << 4; }
    else         { c = (unsigned)tid;      tb4 = 0; }
    unsigned base = 0;
    #pragma unroll
    for (int b = 0; b < 14 - KG; b++)
        base |= ((c >> b) & 1u) << grp.npos[b];

    const float2* __restrict__ gG = &g_ab[grp.gbase][0];
    u64 XP[8], YP[8];

    // ---- gate 0 (scalar, fused with load+pack along local bit 0) ----
    {
        float2 ga = gG[0], gb = gG[1];
        bool sw = (__popc(base & (unsigned)grp.row[0]) & 1) != 0;
        float ax = ga.x, ay = sw ? -ga.y : ga.y;
        float bx = sw ? -gb.x : gb.x, by = gb.y;
        #pragma unroll
        for (int u = 0; u < 8; u++) {
            unsigned i0 = base ^ grp.loc2glob[(u << 1) | tb4];
            unsigned i1 = base ^ grp.loc2glob[(u << 1) | 1 | tb4];
            float x0 = sx[i0], y0 = sy[i0];
            float x1 = sx[i1], y1 = sy[i1];
            float n0x = ax*x0 - ay*y0 - bx*x1 - by*y1;
            float n0y = ax*y0 + ay*x0 - bx*y1 + by*x1;
            float n1x = bx*x0 - by*y0 + ax*x1 + ay*y1;
            float n1y = bx*y0 + by*x0 + ax*y1 - ay*x1;
            PK2(XP[u], n0x, n1x);
            PK2(YP[u], n0y, n1y);
        }
    }

    // ---- gates 1..3: packed stages over slot bits ----
    #pragma unroll
    for (int j = 1; j < 4; j++) {
        float2 ga = gG[2*j], gb = gG[2*j + 1];
        bool sw = (__popc(base & (unsigned)grp.row[j]) & 1) != 0;
        float ax = ga.x, ay = sw ? -ga.y : ga.y;
        float bx = sw ? -gb.x : gb.x, by = gb.y;
        u64 sax, sAy, snAy, sBx, snBx, sby, snby;
        PK2(sax, ax, ax);
        PK2(sAy, ay, ay);   PK2(snAy, -ay, -ay);
        PK2(sBx, bx, bx);   PK2(snBx, -bx, -bx);
        PK2(sby, by, by);   PK2(snby, -by, -by);
        const int bit = 1 << (j - 1);
        #pragma unroll
        for (int u = 0; u < 8; u++) {
            if (u & bit) continue;
            const int v = u | bit;
            u64 px = XP[u], py = YP[u], qx = XP[v], qy = YP[v];
            u64 t0, t1, t2, t3;
            BUTTERFLY2(px, py, qx, qy, t0, t1, t2, t3);
            XP[u] = t0; YP[u] = t1; XP[v] = t2; YP[v] = t3;
        }
    }

    // ---- gate 4 (KG==5 only): cross-thread butterfly via shfl_xor ----
    if (KG == 5) {
        float2 ga = gG[8], gb = gG[9];
        bool b1 = ((__popc(base & (unsigned)grp.row[4]) ^ (tid & 1)) & 1) != 0;
        // own true-bit b: w_own = b ? conj(A) : A ; w_part = b ? B : -conj(B)
        float wox = ga.x, woy = b1 ? -ga.y : ga.y;
        float wpx = b1 ? gb.x : -gb.x, wpy = gb.y;
        u64 swox, swoy, snwoy, swpx, swpy, snwpy;
        PK2(swox, wox, wox);
        PK2(swoy, woy, woy); PK2(snwoy, -woy, -woy);
        PK2(swpx, wpx, wpx);
        PK2(swpy, wpy, wpy); PK2(snwpy, -wpy, -wpy);
        #pragma unroll
        for (int u = 0; u < 8; u++) {
            u64 ox = XP[u], oy = YP[u];
            u64 qx = __shfl_xor_sync(0xffffffffu, ox, 1);
            u64 qy = __shfl_xor_sync(0xffffffffu, oy, 1);
            u64 nx, ny;
            MUL2(nx, snwpy, qy); FMA2(nx, swpx, qx, nx);
            FMA2(nx, snwoy, oy, nx); FMA2(nx, swox, ox, nx);
            MUL2(ny, swpy, qx); FMA2(ny, swpx, qy, ny);
            FMA2(ny, swoy, ox, ny); FMA2(ny, swox, oy, ny);
            XP[u] = nx; YP[u] = ny;
        }
    }

    // ---- unpack + store ----
    #pragma unroll
    for (int u = 0; u < 8; u++) {
        unsigned i0 = base ^ grp.loc2glob[(u << 1) | tb4];
        unsigned i1 = base ^ grp.loc2glob[(u << 1) | 1 | tb4];
        float a0, a1, b0, b1;
        UPK2(a0, a1, XP[u]);
        UPK2(b0, b1, YP[u]);
        sx[i0] = a0; sx[i1] = a1;
        sy[i0] = b0; sy[i1] = b1;
    }
}

__global__ __launch_bounds__(NTHREADS, 1)
void sim_kernel(const float* __restrict__ x, float* __restrict__ out, Tab2 tab) {
    extern __shared__ float sv[];          // [0,DIM): x-plane, [DIM,2*DIM): y-plane
    float* sx = sv;
    float* sy = sv + DIM;
    __shared__ float ec[NQ], es[NQ];
    __shared__ float2 red[NWARPS];

    const int b   = blockIdx.x;
    const int tid = threadIdx.x;

    if (tid < NQ) {
        float h = x[b * NQ + tid] * 1.5707963267948966f;
        float svv, cv;
        sincosf(h, &svv, &cv);
        ec[tid] = cv;
        es[tid] = svv;
    }
    __syncthreads();

    // init: encoded real product state; qubit q at bit (13-q)
    // idx = tid*16 + l : tid -> qubits 0..9, l -> qubits 10..13
    float hi = 1.0f;
    #pragma unroll
    for (int q = 0; q < 10; q++)
        hi *= ((tid >> (9 - q)) & 1) ? es[q] : ec[q];
    #pragma unroll
    for (int l = 0; l < APT; l++) {
        float v = hi;
        #pragma unroll
        for (int q = 10; q < NQ; q++)
            v *= ((l >> (13 - q)) & 1) ? es[q] : ec[q];
        sx[tid * APT + l] = v;
        sy[tid * APT + l] = 0.0f;
    }
    __syncthreads();

    #pragma unroll 1
    for (int l = 0; l < NL; l++) {
        do_group<5>(sx, sy, tab.grp[l * 3 + 0], tid); __syncthreads();
        do_group<5>(sx, sy, tab.grp[l * 3 + 1], tid); __syncthreads();
        do_group<4>(sx, sy, tab.grp[l * 3 + 2], tid); __syncthreads();
    }

    // measurement
    float z0 = 0.0f, z1 = 0.0f;
    #pragma unroll
    for (int l = 0; l < APT; l++) {
        unsigned idx = (unsigned)(tid * APT + l);
        float xr = sx[idx], yi = sy[idx];
        float pr = xr * xr + yi * yi;
        z0 += (__popc(idx & tab.mrow0) & 1) ? -pr : pr;
        z1 += (__popc(idx & tab.mrow1) & 1) ? -pr : pr;
    }
    #pragma unroll
    for (int o = 16; o; o >>= 1) {
        z0 += __shfl_down_sync(0xffffffffu, z0, o);
        z1 += __shfl_down_sync(0xffffffffu, z1, o);
    }
    if ((tid & 31) == 0) red[tid >> 5] = make_float2(z0, z1);
    __syncthreads();
    if (tid == 0) {
        float a0 = 0.0f, a1 = 0.0f;
        #pragma unroll
        for (int w = 0; w < NWARPS; w++) { a0 += red[w].x; a1 += red[w].y; }
        out[b * 2 + 0] = a0;
        out[b * 2 + 1] = a1;
    }
}

extern "C" void kernel_launch(void* const* d_in, const int* in_sizes, int n_in,
                              void* d_out, int out_size) {
    const float* x = (const float*)d_in[0];       // (B, 14)
    const float* w = (const float*)d_in[1];       // (6, 14, 3)
    float* out = (float*)d_out;                   // (B, 2)
    const int B = in_sizes[0] / NQ;

    // --- host: GF(2) frame tracking + per-group echelon tables ---
    Tab2 tab;
    unsigned short R[NQ], Minv[NQ];
    for (int q = 0; q < NQ; q++)
        R[q] = Minv[q] = (unsigned short)(1u << (13 - q));

    for (int l = 0; l < NL; l++) {
        int offs[4] = {0, 5, 10, 14};             // groups of 5,5,4
        for (int gi = 0; gi < 3; gi++) {
            Group& G = tab.grp[l * 3 + gi];
            int off = offs[gi], kg = offs[gi + 1] - offs[gi];
            unsigned short m[5];
            for (int i = 0; i < kg; i++) {
                m[i] = Minv[off + i];
                G.row[i] = R[off + i];
            }
            for (int i = kg; i < 5; i++) G.row[i] = 0;
            G.gbase = (unsigned char)(l * NQ + off);
            // echelonize to find pivot bits
            unsigned red_[5]; int piv[5];
            for (int i = 0; i < kg; i++) {
                unsigned v = m[i];
                for (int j = 0; j < i; j++)
                    if ((v >> piv[j]) & 1u) v ^= red_[j];
                int p = 31 - __builtin_clz(v);    // masks linearly independent
                piv[i] = p; red_[i] = v;
            }
            bool ispiv[14] = {};
            for (int i = 0; i < kg; i++) ispiv[piv[i]] = true;
            int idx = 0;
            for (int bpos = 0; bpos < 14; bpos++)
                if (!ispiv[bpos]) G.npos[idx++] = (unsigned char)bpos;
            while (idx < 10) G.npos[idx++] = 0;
            for (int t = 0; t < 32; t++) {
                unsigned xr = 0;
                for (int i = 0; i < kg; i++)
                    if ((t >> i) & 1) xr ^= m[i];
                G.loc2glob[t] = (unsigned short)(t < (1 << kg) ? xr : 0);
            }
        }
        int r = (l % (NQ - 1)) + 1;
        for (int q = 0; q < NQ; q++) {
            int c = q, t = (q + r) % NQ;
            R[t]    ^= R[c];
            Minv[c] ^= Minv[t];
        }
    }
    tab.mrow0 = R[0];
    tab.mrow1 = R[1];

    cudaFuncSetAttribute(sim_kernel, cudaFuncAttributeMaxDynamicSharedMemorySize,
                         2 * DIM * (int)sizeof(float));

    prep_gates_kernel<<<1, 128>>>(w);
    sim_kernel<<<B, NTHREADS, 2 * DIM * sizeof(float)>>>(x, out, tab);
}

// round 8
// speedup vs baseline: 1.4282x; 1.4282x over previous
#include <cuda_runtime.h>
#include <cstdint>

#define NQ 14
#define NL 6
#define DIM 16384
#define NG (NL * NQ)                 // 84 rotation gates
#define NTHREADS 512
#define AMPS_PER_THREAD (DIM / NTHREADS)      // 32
#define NWARPS (NTHREADS / 32)
#define NGROUPS (NL * 3)             // 3 fused groups per layer (5,5,4)

typedef unsigned long long u64;

// ---- packed f32x2 helpers ----
#define PK2(r, a, b)   asm("mov.b64 %0, {%1,%2};" : "=l"(r) : "f"(a), "f"(b))
#define UPK2(a, b, r)  asm("mov.b64 {%0,%1}, %2;" : "=f"(a), "=f"(b) : "l"(r))
#define FMA2(d, a, b, c) asm("fma.rn.f32x2 %0, %1, %2, %3;" : "=l"(d) : "l"(a), "l"(b), "l"(c))
#define MUL2(d, a, b)    asm("mul.rn.f32x2 %0, %1, %2;" : "=l"(d) : "l"(a), "l"(b))

// Bank swizzle: word address of amplitude i. GF(2)-linear: w(a^b)=w(a)^w(b).
// Bank bits of w(i) = XOR-fold of all 14 bits of i into 5 bits -> any single
// differing index bit flips the bank.
__host__ __device__ __forceinline__ unsigned swz(unsigned i) {
    return i ^ (((i >> 5) ^ (i >> 10)) & 31u);
}

// One fused gate-group: K gates (5 or 4) with commuting targets.
struct Group {
    unsigned short loc2glob[32];  // PRE-SWIZZLED coset offsets (XOR of masks)
    unsigned short row[5];        // parity rows (true-qubit bit), RAW bits
    unsigned char  npos[10];      // non-pivot bit positions (lane bits first,
                                  // chosen with distinct residues mod 5)
    unsigned char  gbase;         // first gate index into g_gates
};
struct Tab2 {
    Group grp[NGROUPS];
    unsigned short mrow0, mrow1;  // measurement parity rows
};

__device__ float2 g_gates[NG][4];   // [g][u00,u01,u10,u11]

__global__ void prep_gates_kernel(const float* __restrict__ w) {
    int g = blockIdx.x * blockDim.x + threadIdx.x;
    if (g >= NG) return;
    float phi   = w[g * 3 + 0];
    float theta = w[g * 3 + 1];
    float omega = w[g * 3 + 2];
    float st, ct;
    sincosf(theta * 0.5f, &st, &ct);
    float ssp, csp, ssm, csm;
    sincosf(0.5f * (phi + omega), &ssp, &csp);
    sincosf(0.5f * (phi - omega), &ssm, &csm);
    g_gates[g][0] = make_float2( csp * ct, -ssp * ct);
    g_gates[g][1] = make_float2(-csm * st, -ssm * st);
    g_gates[g][2] = make_float2( csm * st, -ssm * st);
    g_gates[g][3] = make_float2( csp * ct,  ssp * ct);
}

// Apply one fused group. SoA planes sx/sy, swizzled addressing.
// Gate 0 scalar at load (pack along local bit 0); gates 1..KG-1 packed FMA2.
template<int KG>
__device__ __forceinline__ void do_group(float* __restrict__ sx,
                                         float* __restrict__ sy,
                                         const Group& grp, int tid) {
    const int NCOS = (DIM >> KG) / NTHREADS;   // 1 for KG=5, 2 for KG=4
    const int NU   = 1 << (KG - 1);            // packed slots per coset
    const float2* __restrict__ gm = &g_gates[grp.gbase][0];

    #pragma unroll
    for (int ci = 0; ci < NCOS; ci++) {
        unsigned c = (unsigned)tid + (unsigned)ci * NTHREADS;
        unsigned base = 0;
        #pragma unroll
        for (int b = 0; b < 14 - KG; b++)
            base |= ((c >> b) & 1u) << grp.npos[b];
        const unsigned bsw = swz(base);        // swizzled coset base

        u64 XP[16], YP[16];

        // ---- gate 0 (scalar) fused with load + pack ----
        {
            bool sw = (__popc(base & (unsigned)grp.row[0]) & 1) != 0;
            float2 m0 = gm[0], m1 = gm[1], m2 = gm[2], m3 = gm[3];
            float v00x = sw ? m3.x : m0.x, v00y = sw ? m3.y : m0.y;
            float v01x = sw ? m2.x : m1.x, v01y = sw ? m2.y : m1.y;
            float v10x = sw ? m1.x : m2.x, v10y = sw ? m1.y : m2.y;
            float v11x = sw ? m0.x : m3.x, v11y = sw ? m0.y : m3.y;
            #pragma unroll
            for (int u = 0; u < NU; u++) {
                unsigned i0 = bsw ^ grp.loc2glob[2 * u];
                unsigned i1 = bsw ^ grp.loc2glob[2 * u + 1];
                float x0 = sx[i0], y0 = sy[i0];
                float x1 = sx[i1], y1 = sy[i1];
                float n0x = v00x * x0 - v00y * y0 + v01x * x1 - v01y * y1;
                float n0y = v00x * y0 + v00y * x0 + v01x * y1 + v01y * x1;
                float n1x = v10x * x0 - v10y * y0 + v11x * x1 - v11y * y1;
                float n1y = v10x * y0 + v10y * x0 + v11x * y1 + v11y * x1;
                PK2(XP[u], n0x, n1x);
                PK2(YP[u], n0y, n1y);
            }
        }

        // ---- gates 1..KG-1 (packed FMA2, lane-splat constants) ----
        #pragma unroll
        for (int j = 1; j < KG; j++) {
            bool sw = (__popc(base & (unsigned)grp.row[j]) & 1) != 0;
            float2 m0 = gm[j * 4 + 0], m1 = gm[j * 4 + 1];
            float2 m2 = gm[j * 4 + 2], m3 = gm[j * 4 + 3];
            float v00x = sw ? m3.x : m0.x, v00y = sw ? m3.y : m0.y;
            float v01x = sw ? m2.x : m1.x, v01y = sw ? m2.y : m1.y;
            float v10x = sw ? m1.x : m2.x, v10y = sw ? m1.y : m2.y;
            float v11x = sw ? m0.x : m3.x, v11y = sw ? m0.y : m3.y;
            u64 s00x, s00y, s00n, s01x, s01y, s01n;
            u64 s10x, s10y, s10n, s11x, s11y, s11n;
            PK2(s00x, v00x, v00x); PK2(s00y, v00y, v00y); PK2(s00n, -v00y, -v00y);
            PK2(s01x, v01x, v01x); PK2(s01y, v01y, v01y); PK2(s01n, -v01y, -v01y);
            PK2(s10x, v10x, v10x); PK2(s10y, v10y, v10y); PK2(s10n, -v10y, -v10y);
            PK2(s11x, v11x, v11x); PK2(s11y, v11y, v11y); PK2(s11n, -v11y, -v11y);

            const int bit = 1 << (j - 1);
            #pragma unroll
            for (int u = 0; u < NU; u++) {
                if (u & bit) continue;
                const int w = u | bit;
                u64 px = XP[u], py = YP[u], qx = XP[w], qy = YP[w];
                u64 t0, t1, t2, t3;
                MUL2(t0, s01n, qy); FMA2(t0, s01x, qx, t0);
                FMA2(t0, s00n, py, t0); FMA2(t0, s00x, px, t0);   // n0x
                MUL2(t1, s01y, qx); FMA2(t1, s01x, qy, t1);
                FMA2(t1, s00y, px, t1); FMA2(t1, s00x, py, t1);   // n0y
                MUL2(t2, s11n, qy); FMA2(t2, s11x, qx, t2);
                FMA2(t2, s10n, py, t2); FMA2(t2, s10x, px, t2);   // n1x
                MUL2(t3, s11y, qx); FMA2(t3, s11x, qy, t3);
                FMA2(t3, s10y, px, t3); FMA2(t3, s10x, py, t3);   // n1y
                XP[u] = t0; YP[u] = t1; XP[w] = t2; YP[w] = t3;
            }
        }

        // ---- unpack + store ----
        #pragma unroll
        for (int u = 0; u < NU; u++) {
            unsigned i0 = bsw ^ grp.loc2glob[2 * u];
            unsigned i1 = bsw ^ grp.loc2glob[2 * u + 1];
            float a0, a1, b0, b1;
            UPK2(a0, a1, XP[u]);
            UPK2(b0, b1, YP[u]);
            sx[i0] = a0; sx[i1] = a1;
            sy[i0] = b0; sy[i1] = b1;
        }
    }
}

__global__ __launch_bounds__(NTHREADS, 1)
void sim_kernel(const float* __restrict__ x, float* __restrict__ out, Tab2 tab) {
    extern __shared__ float sv[];          // [0,DIM): x-plane, [DIM,2*DIM): y-plane
    float* sx = sv;
    float* sy = sv + DIM;
    __shared__ float ec[NQ], es[NQ];
    __shared__ float2 red[NWARPS];

    const int b   = blockIdx.x;
    const int tid = threadIdx.x;

    if (tid < NQ) {
        float h = x[b * NQ + tid] * 1.5707963267948966f;
        float svv, cv;
        sincosf(h, &svv, &cv);
        ec[tid] = cv;
        es[tid] = svv;
    }
    __syncthreads();

    // init: encoded real product state; qubit q at bit (13-q)
    float hi = 1.0f;
    #pragma unroll
    for (int q = 0; q < 9; q++)
        hi *= ((tid >> (8 - q)) & 1) ? es[q] : ec[q];
    #pragma unroll
    for (int l = 0; l < AMPS_PER_THREAD; l++) {
        float v = hi;
        #pragma unroll
        for (int q = 9; q < NQ; q++)
            v *= ((l >> (13 - q)) & 1) ? es[q] : ec[q];
        unsigned a = swz((unsigned)(tid * AMPS_PER_THREAD + l));
        sx[a] = v;
        sy[a] = 0.0f;
    }
    __syncthreads();

    #pragma unroll 1
    for (int l = 0; l < NL; l++) {
        do_group<5>(sx, sy, tab.grp[l * 3 + 0], tid); __syncthreads();
        do_group<5>(sx, sy, tab.grp[l * 3 + 1], tid); __syncthreads();
        do_group<4>(sx, sy, tab.grp[l * 3 + 2], tid); __syncthreads();
    }

    // measurement: parity on RAW index, address swizzled
    float z0 = 0.0f, z1 = 0.0f;
    #pragma unroll
    for (int l = 0; l < AMPS_PER_THREAD; l++) {
        unsigned idx = (unsigned)(tid * AMPS_PER_THREAD + l);
        unsigned a = swz(idx);
        float xr = sx[a], yi = sy[a];
        float pr = xr * xr + yi * yi;
        z0 += (__popc(idx & tab.mrow0) & 1) ? -pr : pr;
        z1 += (__popc(idx & tab.mrow1) & 1) ? -pr : pr;
    }
    #pragma unroll
    for (int o = 16; o; o >>= 1) {
        z0 += __shfl_down_sync(0xffffffffu, z0, o);
        z1 += __shfl_down_sync(0xffffffffu, z1, o);
    }
    if ((tid & 31) == 0) red[tid >> 5] = make_float2(z0, z1);
    __syncthreads();
    if (tid == 0) {
        float a0 = 0.0f, a1 = 0.0f;
        #pragma unroll
        for (int w = 0; w < NWARPS; w++) { a0 += red[w].x; a1 += red[w].y; }
        out[b * 2 + 0] = a0;
        out[b * 2 + 1] = a1;
    }
}

extern "C" void kernel_launch(void* const* d_in, const int* in_sizes, int n_in,
                              void* d_out, int out_size) {
    const float* x = (const float*)d_in[0];       // (B, 14)
    const float* w = (const float*)d_in[1];       // (6, 14, 3)
    float* out = (float*)d_out;                   // (B, 2)
    const int B = in_sizes[0] / NQ;

    // --- host: GF(2) frame tracking + per-group echelon tables ---
    Tab2 tab;
    unsigned short R[NQ], Minv[NQ];
    for (int q = 0; q < NQ; q++)
        R[q] = Minv[q] = (unsigned short)(1u << (13 - q));

    for (int l = 0; l < NL; l++) {
        int offs[4] = {0, 5, 10, 14};             // groups of 5,5,4
        for (int gi = 0; gi < 3; gi++) {
            Group& G = tab.grp[l * 3 + gi];
            int off = offs[gi], kg = offs[gi + 1] - offs[gi];
            unsigned short m[5];
            for (int i = 0; i < kg; i++) {
                m[i] = Minv[off + i];
                G.row[i] = R[off + i];
            }
            for (int i = kg; i < 5; i++) G.row[i] = 0;
            G.gbase = (unsigned char)(l * NQ + off);
            // echelonize to find pivot bits (highest-bit pivots)
            unsigned red_[5]; int piv[5];
            for (int i = 0; i < kg; i++) {
                unsigned v = m[i];
                for (int j = 0; j < i; j++)
                    if ((v >> piv[j]) & 1u) v ^= red_[j];
                int p = 31 - __builtin_clz(v);    // masks linearly independent
                piv[i] = p; red_[i] = v;
            }
            bool ispiv[14] = {};
            for (int i = 0; i < kg; i++) ispiv[piv[i]] = true;
            // lane-bit selection: first 5 npos slots are the warp-lane bits of c.
            // pick non-pivot positions with DISTINCT residues mod 5 so bank
            // folds are linearly independent -> conflict-free warp accesses.
            bool used[14] = {}, resUsed[5] = {};
            int npv = 14 - kg;
            int slot = 0;
            unsigned char sel[10];
            // strict pass: distinct residues
            for (int bpos = 0; bpos < 14 && slot < 5; bpos++) {
                if (ispiv[bpos] || used[bpos]) continue;
                int rr = bpos % 5;
                if (resUsed[rr]) continue;
                sel[slot++] = (unsigned char)bpos;
                used[bpos] = true; resUsed[rr] = true;
            }
            // lax pass: fill any remaining lane slots
            for (int bpos = 0; bpos < 14 && slot < 5; bpos++) {
                if (ispiv[bpos] || used[bpos]) continue;
                sel[slot++] = (unsigned char)bpos;
                used[bpos] = true;
            }
            // remaining non-pivot bits in ascending order
            for (int bpos = 0; bpos < 14 && slot < npv; bpos++) {
                if (ispiv[bpos] || used[bpos]) continue;
                sel[slot++] = (unsigned char)bpos;
                used[bpos] = true;
            }
            for (int i = 0; i < npv; i++) G.npos[i] = sel[i];
            for (int i = npv; i < 10; i++) G.npos[i] = 0;
            // local->global XOR offsets, PRE-SWIZZLED (swz is GF(2)-linear)
            for (int t = 0; t < 32; t++) {
                unsigned xr = 0;
                for (int i = 0; i < kg; i++)
                    if ((t >> i) & 1) xr ^= m[i];
                G.loc2glob[t] = (unsigned short)(t < (1 << kg) ? swz(xr) : 0);
            }
        }
        // layer's CNOT ring updates the frame
        int r = (l % (NQ - 1)) + 1;
        for (int q = 0; q < NQ; q++) {
            int c = q, t = (q + r) % NQ;
            R[t]    ^= R[c];
            Minv[c] ^= Minv[t];
        }
    }
    tab.mrow0 = R[0];
    tab.mrow1 = R[1];

    cudaFuncSetAttribute(sim_kernel, cudaFuncAttributeMaxDynamicSharedMemorySize,
                         2 * DIM * (int)sizeof(float));

    prep_gates_kernel<<<1, 128>>>(w);
    sim_kernel<<<B, NTHREADS, 2 * DIM * sizeof(float)>>>(x, out, tab);
}

// round 9
// speedup vs baseline: 1.8248x; 1.2777x over previous
#include <cuda_runtime.h>
#include <cstdint>

#define NQ 14
#define NL 6
#define DIM 16384
#define NG (NL * NQ)                 // 84 rotation gates
#define NTHREADS 512
#define APT (DIM / NTHREADS)         // 32 amps/thread
#define NWARPS (NTHREADS / 32)
#define NGROUPS (NL * 3)             // (5,5,4) per layer

typedef unsigned long long u64;

// ---- packed f32x2 helpers ----
#define PK2(r, a, b)   asm("mov.b64 %0, {%1,%2};" : "=l"(r) : "f"(a), "f"(b))
#define UPK2(a, b, r)  asm("mov.b64 {%0,%1}, %2;" : "=f"(a), "=f"(b) : "l"(r))
#define FMA2(d, a, b, c) asm("fma.rn.f32x2 %0, %1, %2, %3;" : "=l"(d) : "l"(a), "l"(b), "l"(c))
#define MUL2(d, a, b)    asm("mul.rn.f32x2 %0, %1, %2;" : "=l"(d) : "l"(a), "l"(b))

// Bank swizzle (GF(2)-linear): bank = 5-bit XOR-fold of all 14 index bits.
__host__ __device__ constexpr unsigned swz(unsigned i) {
    return i ^ (((i >> 5) ^ (i >> 10)) & 31u);
}

// ================= compile-time boundary tables (circuit structure) =========
// Boundary bd carries diagonal RZ terms: bd=0: phi_0 (fused into init);
// bd=1..5: omega_{bd-1} (frame of layer bd-1) + phi_bd (frame of layer bd).
// Diag pass enumerates i = tid*32 + l: t-coord = low 5 bits, c-coord = tid.
struct BT  { int n; unsigned char b5[28]; unsigned short c9[28]; };
struct BTall { BT b[6]; };

constexpr BTall make_btall() {
    BTall A{};
    unsigned short R[NL + 1][NQ] = {};
    for (int q = 0; q < NQ; q++) R[0][q] = (unsigned short)(1u << (13 - q));
    for (int l = 0; l < NL; l++) {
        unsigned short cur[NQ] = {};
        for (int q = 0; q < NQ; q++) cur[q] = R[l][q];
        int r = (l % (NQ - 1)) + 1;
        for (int q = 0; q < NQ; q++) { int t = (q + r) % NQ; cur[t] ^= cur[q]; }
        for (int q = 0; q < NQ; q++) R[l + 1][q] = cur[q];
    }
    A.b[0].n = NQ;
    for (int q = 0; q < NQ; q++) {
        A.b[0].b5[q] = (unsigned char)(R[0][q] & 31);
        A.b[0].c9[q] = (unsigned short)(R[0][q] >> 5);
    }
    for (int bd = 1; bd < 6; bd++) {
        A.b[bd].n = 2 * NQ;
        for (int q = 0; q < NQ; q++) {
            A.b[bd].b5[q]      = (unsigned char)(R[bd - 1][q] & 31);   // omega terms
            A.b[bd].c9[q]      = (unsigned short)(R[bd - 1][q] >> 5);
            A.b[bd].b5[NQ + q] = (unsigned char)(R[bd][q] & 31);       // phi terms
            A.b[bd].c9[NQ + q] = (unsigned short)(R[bd][q] >> 5);
        }
    }
    return A;
}
constexpr BTall BTABS = make_btall();

// ================= runtime tables ==========================================
struct Grp {
    unsigned short l2g[32];    // pre-swizzled coset offsets
    unsigned short swzn[10];   // swz(1<<npos[b]) for coset base build
    unsigned short crow[5];    // parity(base & R_j) == parity(c & crow[j])
    unsigned short gbase;      // first gate index
};
struct Tab3 {
    Grp g[NGROUPS];
    unsigned short mrow0, mrow1;
};
struct PrepTab { unsigned short widx[6][28]; unsigned char n[6]; };

__device__ float2 g_cs[NG];      // (cos th/2, sin th/2) per gate
__device__ float  g_beta[6][28]; // diagonal half-angles per boundary

__global__ void prep_kernel(const float* __restrict__ w, PrepTab pt) {
    int t = threadIdx.x;
    if (t < NG) {
        float s, c;
        sincosf(0.5f * w[t * 3 + 1], &s, &c);
        g_cs[t] = make_float2(c, s);
    }
    if (t < 6 * 28) {
        int bd = t / 28, k = t % 28;
        g_beta[bd][k] = (k < pt.n[bd]) ? 0.5f * w[pt.widx[bd][k]] : 0.0f;
    }
}

// ---- diagonal angle: gamma scatter (compile-time slots) + 5-bit WHT --------
template<int BD, int K>
__device__ __forceinline__ void accum_g(float (&L)[32], unsigned tid) {
    if constexpr (K >= 0) {
        constexpr unsigned b5 = BTABS.b[BD].b5[K];
        constexpr unsigned c9 = BTABS.b[BD].c9[K];
        float bk = g_beta[BD][K];
        L[b5] += (__popc(tid & c9) & 1) ? bk : -bk;
        accum_g<BD, K - 1>(L, tid);
    }
}

template<int BD>
__device__ __forceinline__ void compute_L(float (&L)[32], unsigned tid) {
    #pragma unroll
    for (int i = 0; i < 32; i++) L[i] = 0.0f;
    accum_g<BD, 27>(L, tid);
    #pragma unroll
    for (int st = 0; st < 5; st++) {
        #pragma unroll
        for (int t = 0; t < 32; t++) {
            if (!(t & (1 << st))) {
                float u = L[t], v = L[t | (1 << st)];
                L[t] = u + v;
                L[t | (1 << st)] = u - v;
            }
        }
    }
}

template<int BD>
__device__ __forceinline__ void diag_pass(float* __restrict__ sx,
                                          float* __restrict__ sy, int tid) {
    float L[32];
    compute_L<BD>(L, (unsigned)tid);
    #pragma unroll
    for (int l = 0; l < 32; l++) {
        unsigned a = swz((unsigned)(tid * APT + l));
        float sL, cL;
        __sincosf(L[l], &sL, &cL);
        float xr = sx[a], yi = sy[a];
        sx[a] = xr * cL - yi * sL;
        sy[a] = xr * sL + yi * cL;
    }
}

// ---- real-RY fused group (K gates, commuting targets) ---------------------
template<int KG>
__device__ __forceinline__ void do_group(float* __restrict__ sx,
                                         float* __restrict__ sy,
                                         const Grp& G, int tid) {
    const int NCOS = (DIM >> KG) / NTHREADS;   // 1 (KG=5), 2 (KG=4)
    const int NU   = 1 << (KG - 1);
    #pragma unroll
    for (int ci = 0; ci < NCOS; ci++) {
        unsigned c = (unsigned)tid + (unsigned)ci * NTHREADS;
        unsigned bsw = 0;
        #pragma unroll
        for (int b = 0; b < 14 - KG; b++)
            if ((c >> b) & 1u) bsw ^= G.swzn[b];

        u64 XP[NU], YP[NU];

        // gate 0 (scalar real RY) fused with load + pack along local bit 0
        {
            float2 cs = g_cs[G.gbase];
            bool a0 = (__popc(c & (unsigned)G.crow[0]) & 1) != 0;
            float se = a0 ? -cs.y : cs.y;
            float cc = cs.x;
            #pragma unroll
            for (int u = 0; u < NU; u++) {
                unsigned i0 = bsw ^ G.l2g[2 * u];
                unsigned i1 = bsw ^ G.l2g[2 * u + 1];
                float x0 = sx[i0], y0 = sy[i0];
                float x1 = sx[i1], y1 = sy[i1];
                float n0x = cc * x0 - se * x1;
                float n0y = cc * y0 - se * y1;
                float n1x = se * x0 + cc * x1;
                float n1y = se * y0 + cc * y1;
                PK2(XP[u], n0x, n1x);
                PK2(YP[u], n0y, n1y);
            }
        }

        // gates 1..KG-1: packed real butterflies (8 FMA2-slot ops each)
        #pragma unroll
        for (int j = 1; j < KG; j++) {
            float2 cs = g_cs[G.gbase + j];
            bool aj = (__popc(c & (unsigned)G.crow[j]) & 1) != 0;
            float se = aj ? -cs.y : cs.y;
            u64 c2, s2, ns2;
            PK2(c2, cs.x, cs.x);
            PK2(s2, se, se);
            PK2(ns2, -se, -se);
            const int bit = 1 << (j - 1);
            #pragma unroll
            for (int u = 0; u < NU; u++) {
                if (u & bit) continue;
                const int v = u | bit;
                u64 px = XP[u], py = YP[u], qx = XP[v], qy = YP[v];
                u64 t0, t1, t2, t3;
                MUL2(t0, ns2, qx); FMA2(t0, c2, px, t0);   // n_p.x
                MUL2(t1, ns2, qy); FMA2(t1, c2, py, t1);   // n_p.y
                MUL2(t2, s2,  px); FMA2(t2, c2, qx, t2);   // n_q.x
                MUL2(t3, s2,  py); FMA2(t3, c2, qy, t3);   // n_q.y
                XP[u] = t0; YP[u] = t1; XP[v] = t2; YP[v] = t3;
            }
        }

        #pragma unroll
        for (int u = 0; u < NU; u++) {
            unsigned i0 = bsw ^ G.l2g[2 * u];
            unsigned i1 = bsw ^ G.l2g[2 * u + 1];
            float a0, a1, b0, b1;
            UPK2(a0, a1, XP[u]);
            UPK2(b0, b1, YP[u]);
            sx[i0] = a0; sx[i1] = a1;
            sy[i0] = b0; sy[i1] = b1;
        }
    }
}

__global__ __launch_bounds__(NTHREADS, 1)
void sim_kernel(const float* __restrict__ x, float* __restrict__ out, Tab3 tab) {
    extern __shared__ float sv[];
    float* sx = sv;
    float* sy = sv + DIM;
    __shared__ float ec[NQ], es[NQ];
    __shared__ float2 red[NWARPS];

    const int b   = blockIdx.x;
    const int tid = threadIdx.x;

    if (tid < NQ) {
        float h = x[b * NQ + tid] * 1.5707963267948966f;
        float svv, cv;
        sincosf(h, &svv, &cv);
        ec[tid] = cv;
        es[tid] = svv;
    }
    __syncthreads();

    // init: encoded real product state x phi_0 diagonal phases (BD=0)
    {
        float L[32];
        compute_L<0>(L, (unsigned)tid);
        float hi = 1.0f;
        #pragma unroll
        for (int q = 0; q < 9; q++)
            hi *= ((tid >> (8 - q)) & 1) ? es[q] : ec[q];
        #pragma unroll
        for (int l = 0; l < APT; l++) {
            float v = hi;
            #pragma unroll
            for (int q = 9; q < NQ; q++)
                v *= ((l >> (13 - q)) & 1) ? es[q] : ec[q];
            unsigned a = swz((unsigned)(tid * APT + l));
            float sL, cL;
            __sincosf(L[l], &sL, &cL);
            sx[a] = v * cL;
            sy[a] = v * sL;
        }
    }
    __syncthreads();

    #define LAYER(l) \
        do_group<5>(sx, sy, tab.g[(l)*3 + 0], tid); __syncthreads(); \
        do_group<5>(sx, sy, tab.g[(l)*3 + 1], tid); __syncthreads(); \
        do_group<4>(sx, sy, tab.g[(l)*3 + 2], tid); __syncthreads();

    LAYER(0)
    diag_pass<1>(sx, sy, tid); __syncthreads();
    LAYER(1)
    diag_pass<2>(sx, sy, tid); __syncthreads();
    LAYER(2)
    diag_pass<3>(sx, sy, tid); __syncthreads();
    LAYER(3)
    diag_pass<4>(sx, sy, tid); __syncthreads();
    LAYER(4)
    diag_pass<5>(sx, sy, tid); __syncthreads();
    LAYER(5)
    // omega_5 diagonal dropped: |amp|^2 is phase-invariant.
    #undef LAYER

    // measurement
    float z0 = 0.0f, z1 = 0.0f;
    #pragma unroll
    for (int l = 0; l < APT; l++) {
        unsigned idx = (unsigned)(tid * APT + l);
        unsigned a = swz(idx);
        float xr = sx[a], yi = sy[a];
        float pr = xr * xr + yi * yi;
        z0 += (__popc(idx & tab.mrow0) & 1) ? -pr : pr;
        z1 += (__popc(idx & tab.mrow1) & 1) ? -pr : pr;
    }
    #pragma unroll
    for (int o = 16; o; o >>= 1) {
        z0 += __shfl_down_sync(0xffffffffu, z0, o);
        z1 += __shfl_down_sync(0xffffffffu, z1, o);
    }
    if ((tid & 31) == 0) red[tid >> 5] = make_float2(z0, z1);
    __syncthreads();
    if (tid == 0) {
        float a0 = 0.0f, a1 = 0.0f;
        #pragma unroll
        for (int w = 0; w < NWARPS; w++) { a0 += red[w].x; a1 += red[w].y; }
        out[b * 2 + 0] = a0;
        out[b * 2 + 1] = a1;
    }
}

extern "C" void kernel_launch(void* const* d_in, const int* in_sizes, int n_in,
                              void* d_out, int out_size) {
    const float* x = (const float*)d_in[0];       // (B, 14)
    const float* w = (const float*)d_in[1];       // (6, 14, 3)
    float* out = (float*)d_out;                   // (B, 2)
    const int B = in_sizes[0] / NQ;

    // --- host: frame evolution + group tables ---
    Tab3 tab;
    unsigned short R[NL + 1][NQ], Minv[NQ];
    for (int q = 0; q < NQ; q++)
        R[0][q] = Minv[q] = (unsigned short)(1u << (13 - q));
    for (int l = 0; l < NL; l++) {
        unsigned short cur[NQ];
        for (int q = 0; q < NQ; q++) cur[q] = R[l][q];
        int r = (l % (NQ - 1)) + 1;
        for (int q = 0; q < NQ; q++) { int t = (q + r) % NQ; cur[t] ^= cur[q]; }
        for (int q = 0; q < NQ; q++) R[l + 1][q] = cur[q];
    }

    {
        unsigned short Mi[NQ];
        for (int q = 0; q < NQ; q++) Mi[q] = Minv[q];
        for (int l = 0; l < NL; l++) {
            int offs[4] = {0, 5, 10, 14};
            for (int gi = 0; gi < 3; gi++) {
                Grp& G = tab.g[l * 3 + gi];
                int off = offs[gi], kg = offs[gi + 1] - offs[gi];
                unsigned short m[5], rr[5];
                for (int i = 0; i < kg; i++) { m[i] = Mi[off + i]; rr[i] = R[l][off + i]; }
                G.gbase = (unsigned short)(l * NQ + off);
                // echelonize masks for pivot bits
                unsigned red_[5]; int piv[5];
                for (int i = 0; i < kg; i++) {
                    unsigned v = m[i];
                    for (int j = 0; j < i; j++)
                        if ((v >> piv[j]) & 1u) v ^= red_[j];
                    int p = 31 - __builtin_clz(v);
                    piv[i] = p; red_[i] = v;
                }
                bool ispiv[14] = {};
                for (int i = 0; i < kg; i++) ispiv[piv[i]] = true;
                // lane bits (first 5 slots) with distinct residues mod 5
                bool used[14] = {}, resUsed[5] = {};
                int npv = 14 - kg, slot = 0;
                unsigned char sel[10];
                for (int bp = 0; bp < 14 && slot < 5; bp++) {
                    if (ispiv[bp] || used[bp]) continue;
                    int rrr = bp % 5;
                    if (resUsed[rrr]) continue;
                    sel[slot++] = (unsigned char)bp; used[bp] = true; resUsed[rrr] = true;
                }
                for (int bp = 0; bp < 14 && slot < 5; bp++) {
                    if (ispiv[bp] || used[bp]) continue;
                    sel[slot++] = (unsigned char)bp; used[bp] = true;
                }
                for (int bp = 0; bp < 14 && slot < npv; bp++) {
                    if (ispiv[bp] || used[bp]) continue;
                    sel[slot++] = (unsigned char)bp; used[bp] = true;
                }
                for (int i = 0; i < npv; i++) G.swzn[i] = (unsigned short)swz(1u << sel[i]);
                for (int i = npv; i < 10; i++) G.swzn[i] = 0;
                for (int j = 0; j < kg; j++) {
                    unsigned cm = 0;
                    for (int i = 0; i < npv; i++)
                        if ((rr[j] >> sel[i]) & 1u) cm |= 1u << i;
                    G.crow[j] = (unsigned short)cm;
                }
                for (int j = kg; j < 5; j++) G.crow[j] = 0;
                for (int t = 0; t < 32; t++) {
                    unsigned xr = 0;
                    for (int i = 0; i < kg; i++)
                        if ((t >> i) & 1) xr ^= m[i];
                    G.l2g[t] = (unsigned short)(t < (1 << kg) ? swz(xr) : 0);
                }
            }
            // CNOT ring updates Minv (columns of T^-1)
            int r = (l % (NQ - 1)) + 1;
            for (int q = 0; q < NQ; q++) {
                int t = (q + r) % NQ;
                Mi[q] ^= Mi[t];
            }
        }
    }
    tab.mrow0 = R[NL][0];
    tab.mrow1 = R[NL][1];

    // --- prep table: beta weight indices per boundary ---
    PrepTab pt;
    pt.n[0] = NQ;
    for (int q = 0; q < NQ; q++)
        pt.widx[0][q] = (unsigned short)((0 * NQ + q) * 3 + 0);        // phi_0
    for (int k = NQ; k < 28; k++) pt.widx[0][k] = 0;
    for (int bd = 1; bd < 6; bd++) {
        pt.n[bd] = 2 * NQ;
        for (int q = 0; q < NQ; q++) {
            pt.widx[bd][q]      = (unsigned short)(((bd - 1) * NQ + q) * 3 + 2); // omega_{bd-1}
            pt.widx[bd][NQ + q] = (unsigned short)((bd * NQ + q) * 3 + 0);       // phi_bd
        }
    }

    cudaFuncSetAttribute(sim_kernel, cudaFuncAttributeMaxDynamicSharedMemorySize,
                         2 * DIM * (int)sizeof(float));

    prep_kernel<<<1, 256>>>(w, pt);
    sim_kernel<<<B, NTHREADS, 2 * DIM * sizeof(float)>>>(x, out, tab);
}

// round 16
// speedup vs baseline: 2.0426x; 1.1193x over previous
#include <cuda_runtime.h>
#include <cstdint>

#define NQ 14
#define NL 6
#define DIM 16384
#define NG (NL * NQ)                 // 84 rotation gates
#define NTHREADS 512
#define APT (DIM / NTHREADS)         // 32 amps/thread
#define NWARPS (NTHREADS / 32)

typedef unsigned long long u64;

// ---- packed f32x2 helpers ----
#define PK2(r, a, b)   asm("mov.b64 %0, {%1,%2};" : "=l"(r) : "f"(a), "f"(b))
#define UPK2(a, b, r)  asm("mov.b64 {%0,%1}, %2;" : "=f"(a), "=f"(b) : "l"(r))
#define FMA2(d, a, b, c) asm("fma.rn.f32x2 %0, %1, %2, %3;" : "=l"(d) : "l"(a), "l"(b), "l"(c))
#define MUL2(d, a, b)    asm("mul.rn.f32x2 %0, %1, %2;" : "=l"(d) : "l"(a), "l"(b))

// Bank swizzle (GF(2)-linear): bank = 5-bit XOR-fold of all 14 index bits.
__host__ __device__ constexpr unsigned swz(unsigned i) {
    return i ^ (((i >> 5) ^ (i >> 10)) & 31u);
}
constexpr int cpopc(unsigned v) { int c = 0; while (v) { c += (int)(v & 1u); v >>= 1; } return c; }

// ============ compile-time master table (single source of truth) ===========
struct CTGrp {
    unsigned short l2g[32];    // pre-swizzled coset offsets
    unsigned short swzn[10];   // swz(1<<sel[b]) for coset base build
    unsigned short crow[5];    // gate parity rows projected onto c-bits
    unsigned short dslot[28];  // fused-diag: 4-bit local WHT slot per term
    unsigned short dcm[28];    // fused-diag: c-parity mask per term
    unsigned mpar0, mpar1;     // fused-meas: per-slot parity bits (group 17)
    unsigned short mcm0, mcm1; // fused-meas: c-parity masks (group 17)
    int kg;                    // gates in group (5 or 4)
    int gbase;                 // first gate index
    int bd;                    // fused boundary index (1..5) or 0
};
struct CTTab {
    CTGrp g[18];
    unsigned mrow0, mrow1;
    unsigned short phi0row[NQ];  // identity-frame rows for init diag
};

constexpr CTTab make_ct() {
    CTTab T{};
    unsigned short R[NL + 1][NQ] = {};
    for (int q = 0; q < NQ; q++) R[0][q] = (unsigned short)(1u << (13 - q));
    for (int l = 0; l < NL; l++) {
        for (int q = 0; q < NQ; q++) R[l + 1][q] = R[l][q];
        int r = (l % (NQ - 1)) + 1;
        for (int q = 0; q < NQ; q++) { int t = (q + r) % NQ; R[l + 1][t] ^= R[l + 1][q]; }
    }
    unsigned short Mi[NQ] = {};
    for (int q = 0; q < NQ; q++) Mi[q] = (unsigned short)(1u << (13 - q));

    for (int l = 0; l < NL; l++) {
        int offs[4] = {0, 5, 10, 14};
        for (int gi = 0; gi < 3; gi++) {
            CTGrp& G = T.g[l * 3 + gi];
            int off = offs[gi], kg = offs[gi + 1] - offs[gi];
            unsigned short m[5] = {}, rr[5] = {};
            for (int i = 0; i < kg; i++) { m[i] = Mi[off + i]; rr[i] = R[l][off + i]; }
            G.kg = kg; G.gbase = l * NQ + off; G.bd = 0;
            // echelonize masks -> pivot bits
            unsigned red_[5] = {}; int piv[5] = {};
            for (int i = 0; i < kg; i++) {
                unsigned v = m[i];
                for (int j = 0; j < i; j++)
                    if ((v >> piv[j]) & 1u) v ^= red_[j];
                int p = 13; while (p > 0 && !((v >> p) & 1u)) p--;
                piv[i] = p; red_[i] = v;
            }
            bool ispiv[14] = {};
            for (int i = 0; i < kg; i++) ispiv[piv[i]] = true;
            // lane bits first, distinct residues mod 5 (conflict-free banks)
            bool used[14] = {}, resUsed[5] = {};
            int npv = 14 - kg, slot = 0;
            int sel[10] = {};
            for (int bp = 0; bp < 14 && slot < 5; bp++) {
                if (ispiv[bp] || used[bp]) continue;
                int rrr = bp % 5;
                if (resUsed[rrr]) continue;
                sel[slot++] = bp; used[bp] = true; resUsed[rrr] = true;
            }
            for (int bp = 0; bp < 14 && slot < 5; bp++) {
                if (ispiv[bp] || used[bp]) continue;
                sel[slot++] = bp; used[bp] = true;
            }
            for (int bp = 0; bp < 14 && slot < npv; bp++) {
                if (ispiv[bp] || used[bp]) continue;
                sel[slot++] = bp; used[bp] = true;
            }
            for (int i = 0; i < npv; i++) G.swzn[i] = (unsigned short)swz(1u << sel[i]);
            for (int j = 0; j < kg; j++) {
                unsigned cm = 0;
                for (int i = 0; i < npv; i++)
                    if ((rr[j] >> sel[i]) & 1u) cm |= 1u << i;
                G.crow[j] = (unsigned short)cm;
            }
            for (int t = 0; t < (1 << kg); t++) {
                unsigned xr = 0;
                for (int i = 0; i < kg; i++)
                    if ((t >> i) & 1) xr ^= m[i];
                G.l2g[t] = (unsigned short)swz(xr);
            }
            // fused diagonal at store of last group of layers 0..4:
            // boundary bd=l+1 = omega_l (frame R[l]) + phi_{l+1} (frame R[l+1])
            if (gi == 2 && l < NL - 1) {
                G.bd = l + 1;
                for (int k = 0; k < 28; k++) {
                    unsigned row = (k < 14) ? (unsigned)R[l][k] : (unsigned)R[l + 1][k - 14];
                    unsigned sl = 0;
                    for (int i = 0; i < kg; i++)
                        if (cpopc(m[i] & row) & 1) sl |= 1u << i;
                    unsigned cm = 0;
                    for (int b = 0; b < npv; b++)
                        if ((row >> sel[b]) & 1u) cm |= 1u << b;
                    G.dslot[k] = (unsigned short)sl;
                    G.dcm[k]   = (unsigned short)cm;
                }
            }
            // fused measurement at the FINAL group (l=NL-1, gi=2):
            // sign(i) = parity(c & mcm) ^ parity(xr_t & mrow), both static
            if (gi == 2 && l == NL - 1) {
                unsigned m0 = R[NL][0], m1 = R[NL][1];
                for (int t = 0; t < (1 << kg); t++) {
                    unsigned xr = 0;
                    for (int i = 0; i < kg; i++)
                        if ((t >> i) & 1) xr ^= m[i];
                    if (cpopc(xr & m0) & 1) G.mpar0 |= 1u << t;
                    if (cpopc(xr & m1) & 1) G.mpar1 |= 1u << t;
                }
                unsigned cm0 = 0, cm1 = 0;
                for (int b = 0; b < npv; b++) {
                    if ((m0 >> sel[b]) & 1u) cm0 |= 1u << b;
                    if ((m1 >> sel[b]) & 1u) cm1 |= 1u << b;
                }
                G.mcm0 = (unsigned short)cm0;
                G.mcm1 = (unsigned short)cm1;
            }
        }
        int r = (l % (NQ - 1)) + 1;
        for (int q = 0; q < NQ; q++) { int t = (q + r) % NQ; Mi[q] ^= Mi[t]; }
    }
    T.mrow0 = R[NL][0];
    T.mrow1 = R[NL][1];
    for (int q = 0; q < NQ; q++) T.phi0row[q] = R[0][q];
    return T;
}
constexpr CTTab CT = make_ct();

// ============ runtime tables (copied from CT on host) ======================
struct Grp {
    unsigned short l2g[32];
    unsigned short swzn[10];
    unsigned short crow[5];
    unsigned short gbase;
};
struct Tab3 {
    Grp g[18];
};
struct PrepTab { unsigned short widx[6][28]; unsigned char n[6]; };

__device__ float2 g_cs[NG];      // (cos th/2, sin th/2) per gate
__device__ float  g_beta[6][28]; // diagonal half-angles per boundary

__global__ void prep_kernel(const float* __restrict__ w, PrepTab pt) {
    int t = threadIdx.x;
    if (t < NG) {
        float s, c;
        sincosf(0.5f * w[t * 3 + 1], &s, &c);
        g_cs[t] = make_float2(c, s);
    }
    if (t < 6 * 28) {
        int bd = t / 28, k = t % 28;
        g_beta[bd][k] = (k < pt.n[bd]) ? 0.5f * w[pt.widx[bd][k]] : 0.0f;
    }
}

// ---- fused-diag scatter: compile-time slots (register-indexable) ----------
template<int GID, int K>
__device__ __forceinline__ void accum_d(float (&L)[16], unsigned c) {
    if constexpr (K >= 0) {
        constexpr unsigned slot = CT.g[GID].dslot[K];
        constexpr unsigned cm   = CT.g[GID].dcm[K];
        constexpr int bd        = CT.g[GID].bd;
        float bk = g_beta[bd][K];
        L[slot] += (__popc(c & cm) & 1) ? bk : -bk;
        accum_d<GID, K - 1>(L, c);
    }
}

// ---- real-RY fused group; optional diag / measurement at store ------------
template<int GID>
__device__ __forceinline__ void do_group(float* __restrict__ sx,
                                         float* __restrict__ sy,
                                         const Grp& G, int tid,
                                         float* zz0, float* zz1) {
    constexpr int KG   = CT.g[GID].kg;
    constexpr int NCOS = (DIM >> KG) / NTHREADS;   // 1 (KG=5), 2 (KG=4)
    constexpr int NU   = 1 << (KG - 1);
    constexpr int BD   = CT.g[GID].bd;
    constexpr bool MEAS = (GID == 17);

    #pragma unroll
    for (int ci = 0; ci < NCOS; ci++) {
        unsigned c = (unsigned)tid + (unsigned)ci * NTHREADS;
        unsigned bsw = 0;
        #pragma unroll
        for (int b = 0; b < 14 - KG; b++)
            if ((c >> b) & 1u) bsw ^= G.swzn[b];

        u64 XP[NU], YP[NU];

        // gate 0 (scalar real RY) fused with load + pack along local bit 0
        {
            float2 cs = g_cs[G.gbase];
            bool a0 = (__popc(c & (unsigned)G.crow[0]) & 1) != 0;
            float se = a0 ? -cs.y : cs.y;
            float cc = cs.x;
            #pragma unroll
            for (int u = 0; u < NU; u++) {
                unsigned i0 = bsw ^ G.l2g[2 * u];
                unsigned i1 = bsw ^ G.l2g[2 * u + 1];
                float x0 = sx[i0], y0 = sy[i0];
                float x1 = sx[i1], y1 = sy[i1];
                float n0x = cc * x0 - se * x1;
                float n0y = cc * y0 - se * y1;
                float n1x = se * x0 + cc * x1;
                float n1y = se * y0 + cc * y1;
                PK2(XP[u], n0x, n1x);
                PK2(YP[u], n0y, n1y);
            }
        }

        // gates 1..KG-1: packed real butterflies
        #pragma unroll
        for (int j = 1; j < KG; j++) {
            float2 cs = g_cs[G.gbase + j];
            bool aj = (__popc(c & (unsigned)G.crow[j]) & 1) != 0;
            float se = aj ? -cs.y : cs.y;
            u64 c2, s2, ns2;
            PK2(c2, cs.x, cs.x);
            PK2(s2, se, se);
            PK2(ns2, -se, -se);
            const int bit = 1 << (j - 1);
            #pragma unroll
            for (int u = 0; u < NU; u++) {
                if (u & bit) continue;
                const int v = u | bit;
                u64 px = XP[u], py = YP[u], qx = XP[v], qy = YP[v];
                u64 t0, t1, t2, t3;
                MUL2(t0, ns2, qx); FMA2(t0, c2, px, t0);
                MUL2(t1, ns2, qy); FMA2(t1, c2, py, t1);
                MUL2(t2, s2,  px); FMA2(t2, c2, qx, t2);
                MUL2(t3, s2,  py); FMA2(t3, c2, qy, t3);
                XP[u] = t0; YP[u] = t1; XP[v] = t2; YP[v] = t3;
            }
        }

        // fused boundary diagonal (last group of layers 0..4): phase at store
        if constexpr (BD > 0) {
            float L[16];
            #pragma unroll
            for (int i = 0; i < 16; i++) L[i] = 0.0f;
            accum_d<GID, 27>(L, c);
            #pragma unroll
            for (int st = 0; st < 4; st++) {
                #pragma unroll
                for (int t = 0; t < 16; t++) {
                    if (!(t & (1 << st))) {
                        float uu = L[t], vv = L[t | (1 << st)];
                        L[t] = uu + vv;
                        L[t | (1 << st)] = uu - vv;
                    }
                }
            }
            #pragma unroll
            for (int u = 0; u < NU; u++) {
                float s0, c0, s1, c1;
                __sincosf(L[2 * u],     &s0, &c0);
                __sincosf(L[2 * u + 1], &s1, &c1);
                u64 C, S, NS2;
                PK2(C, c0, c1); PK2(S, s0, s1); PK2(NS2, -s0, -s1);
                u64 nx, ny;
                MUL2(nx, NS2, YP[u]); FMA2(nx, C, XP[u], nx);
                MUL2(ny, S,  XP[u]); FMA2(ny, C, YP[u], ny);
                XP[u] = nx; YP[u] = ny;
            }
        }

        if constexpr (MEAS) {
            // fused measurement: |amp|^2 with static per-slot parity signs;
            // final state never stored (nothing reads it afterwards).
            constexpr unsigned mp0 = CT.g[GID].mpar0;
            constexpr unsigned mp1 = CT.g[GID].mpar1;
            constexpr unsigned cm0 = CT.g[GID].mcm0;
            constexpr unsigned cm1 = CT.g[GID].mcm1;
            float z0c = 0.0f, z1c = 0.0f;
            #pragma unroll
            for (int u = 0; u < NU; u++) {
                u64 PR;
                MUL2(PR, XP[u], XP[u]);
                FMA2(PR, YP[u], YP[u], PR);
                float p0, p1;
                UPK2(p0, p1, PR);
                z0c += ((mp0 >> (2 * u)) & 1)     ? -p0 : p0;
                z0c += ((mp0 >> (2 * u + 1)) & 1) ? -p1 : p1;
                z1c += ((mp1 >> (2 * u)) & 1)     ? -p0 : p0;
                z1c += ((mp1 >> (2 * u + 1)) & 1) ? -p1 : p1;
            }
            bool s0 = (__popc(c & cm0) & 1) != 0;
            bool s1 = (__popc(c & cm1) & 1) != 0;
            *zz0 += s0 ? -z0c : z0c;
            *zz1 += s1 ? -z1c : z1c;
        } else {
            #pragma unroll
            for (int u = 0; u < NU; u++) {
                unsigned i0 = bsw ^ G.l2g[2 * u];
                unsigned i1 = bsw ^ G.l2g[2 * u + 1];
                float a0, a1, b0, b1;
                UPK2(a0, a1, XP[u]);
                UPK2(b0, b1, YP[u]);
                sx[i0] = a0; sx[i1] = a1;
                sy[i0] = b0; sy[i1] = b1;
            }
        }
    }
}

__global__ __launch_bounds__(NTHREADS, 1)
void sim_kernel(const float* __restrict__ x, float* __restrict__ out, Tab3 tab) {
    extern __shared__ float sv[];
    float* sx = sv;
    float* sy = sv + DIM;
    __shared__ float ec[NQ], es[NQ];
    __shared__ float2 red[NWARPS];

    const int b   = blockIdx.x;
    const int tid = threadIdx.x;

    if (tid < NQ) {
        float h = x[b * NQ + tid] * 1.5707963267948966f;
        float svv, cv;
        sincosf(h, &svv, &cv);
        ec[tid] = cv;
        es[tid] = svv;
    }
    __syncthreads();

    // init: encoded real product state x phi_0 diagonal (identity frame:
    // rows are single bits; i = tid*32 + l, qubit q at bit (13-q))
    {
        float Lb = 0.0f;
        #pragma unroll
        for (int q = 0; q < 9; q++)
            Lb += ((tid >> (8 - q)) & 1) ? g_beta[0][q] : -g_beta[0][q];
        float hi = 1.0f;
        #pragma unroll
        for (int q = 0; q < 9; q++)
            hi *= ((tid >> (8 - q)) & 1) ? es[q] : ec[q];
        #pragma unroll
        for (int l = 0; l < APT; l++) {
            float v = hi;
            float La = Lb;
            #pragma unroll
            for (int q = 9; q < NQ; q++) {
                bool bit = ((l >> (13 - q)) & 1) != 0;
                v  *= bit ? es[q] : ec[q];
                La += bit ? g_beta[0][q] : -g_beta[0][q];
            }
            unsigned a = swz((unsigned)(tid * APT + l));
            float sL, cL;
            __sincosf(La, &sL, &cL);
            sx[a] = v * cL;
            sy[a] = v * sL;
        }
    }
    __syncthreads();

    float z0 = 0.0f, z1 = 0.0f;

    // 18 gate passes; boundary diagonals fused into groups 2,5,8,11,14;
    // measurement fused into group 17 (no final store/reload).
    #define DG(i) do_group<i>(sx, sy, tab.g[i], tid, &z0, &z1); __syncthreads();
    DG(0)  DG(1)  DG(2)
    DG(3)  DG(4)  DG(5)
    DG(6)  DG(7)  DG(8)
    DG(9)  DG(10) DG(11)
    DG(12) DG(13) DG(14)
    DG(15) DG(16)
    do_group<17>(sx, sy, tab.g[17], tid, &z0, &z1);
    #undef DG
    // omega_5 diagonal dropped: |amp|^2 is phase-invariant.

    // cross-warp reduction
    #pragma unroll
    for (int o = 16; o; o >>= 1) {
        z0 += __shfl_down_sync(0xffffffffu, z0, o);
        z1 += __shfl_down_sync(0xffffffffu, z1, o);
    }
    if ((tid & 31) == 0) red[tid >> 5] = make_float2(z0, z1);
    __syncthreads();
    if (tid == 0) {
        float a0 = 0.0f, a1 = 0.0f;
        #pragma unroll
        for (int w = 0; w < NWARPS; w++) { a0 += red[w].x; a1 += red[w].y; }
        out[b * 2 + 0] = a0;
        out[b * 2 + 1] = a1;
    }
}

extern "C" void kernel_launch(void* const* d_in, const int* in_sizes, int n_in,
                              void* d_out, int out_size) {
    const float* x = (const float*)d_in[0];       // (B, 14)
    const float* w = (const float*)d_in[1];       // (6, 14, 3)
    float* out = (float*)d_out;                   // (B, 2)
    const int B = in_sizes[0] / NQ;

    // runtime tables copied from the compile-time master (single source)
    Tab3 tab;
    for (int g = 0; g < 18; g++) {
        for (int t = 0; t < 32; t++) tab.g[g].l2g[t]  = CT.g[g].l2g[t];
        for (int t = 0; t < 10; t++) tab.g[g].swzn[t] = CT.g[g].swzn[t];
        for (int t = 0; t < 5;  t++) tab.g[g].crow[t] = CT.g[g].crow[t];
        tab.g[g].gbase = (unsigned short)CT.g[g].gbase;
    }

    // beta weight indices per boundary
    PrepTab pt;
    pt.n[0] = NQ;
    for (int q = 0; q < NQ; q++)
        pt.widx[0][q] = (unsigned short)((0 * NQ + q) * 3 + 0);        // phi_0
    for (int k = NQ; k < 28; k++) pt.widx[0][k] = 0;
    for (int bd = 1; bd < 6; bd++) {
        pt.n[bd] = 2 * NQ;
        for (int q = 0; q < NQ; q++) {
            pt.widx[bd][q]      = (unsigned short)(((bd - 1) * NQ + q) * 3 + 2); // omega_{bd-1}
            pt.widx[bd][NQ + q] = (unsigned short)((bd * NQ + q) * 3 + 0);       // phi_bd
        }
    }

    cudaFuncSetAttribute(sim_kernel, cudaFuncAttributeMaxDynamicSharedMemorySize,
                         2 * DIM * (int)sizeof(float));

    prep_kernel<<<1, 256>>>(w, pt);
    sim_kernel<<<B, NTHREADS, 2 * DIM * sizeof(float)>>>(x, out, tab);
}